// round 16
// baseline (speedup 1.0000x reference)
#include <cuda_runtime.h>
#include <math.h>
#include <float.h>

#define G 20
#define GC (G * G * G)   // 8000
#define NB 4             // batches
#define NCB 8            // cloud*NB + b
#define NPC 8192         // max points per (cloud,batch)
#define GMIN (-5.0f)
#define GH 0.5f
#define GINV 2.0f
#define SCANPER 32       // 256*32 = 8192 >= GC

// Static scratch (no cudaMalloc). Zero-initialized at load; scatter_kernel
// re-zeroes g_cnt and search_kernel re-zeroes g_done each execution.
__device__ int g_cnt[NCB][GC];
__device__ int g_start[NCB][GC + 1];
__device__ int g_cid[NCB][NPC];
__device__ int g_rnk[NCB][NPC];
__device__ float4 g_pts[NCB][NPC];  // cell-sorted (x, y, z, |p|^2/2)
__device__ float g_part[512];
__device__ unsigned g_done = 0;

__device__ __forceinline__ int cellof(float x) {
    int c = (int)((x - GMIN) * GINV);
    return min(G - 1, max(0, c));
}

// ---------- count: cell id + rank per point (both clouds) ----------
__global__ __launch_bounds__(256) void count_kernel(const float* __restrict__ in1,
                                                    const float* __restrict__ in2,
                                                    int N, int M) {
    const int i = blockIdx.x * 256 + threadIdx.x;
    const int tot1 = NB * N;
    if (i >= tot1 + NB * M) return;
    const float* p;
    int cb, slot;
    if (i < tot1) { cb = i / N; slot = i - cb * N; p = in1 + (size_t)i * 3; }
    else {
        int j = i - tot1;
        cb = NB + j / M;
        slot = j - (cb - NB) * M;
        p = in2 + (size_t)j * 3;
    }
    const int cid = (cellof(p[2]) * G + cellof(p[1])) * G + cellof(p[0]);
    g_cid[cb][slot] = cid;
    g_rnk[cb][slot] = atomicAdd(&g_cnt[cb][cid], 1);
}

// ---------- scan: one block per (cloud,batch) ----------
__global__ __launch_bounds__(256) void scan_kernel(int N, int M) {
    const int cb = blockIdx.x;
    const int tid = threadIdx.x;
    const int base = tid * SCANPER;
    int loc = 0;
#pragma unroll 4
    for (int i = 0; i < SCANPER; i++) {
        int c = base + i;
        if (c < GC) loc += g_cnt[cb][c];
    }
    __shared__ int sh[256];
    sh[tid] = loc;
    __syncthreads();
    for (int off = 1; off < 256; off <<= 1) {
        int v = (tid >= off) ? sh[tid - off] : 0;
        __syncthreads();
        sh[tid] += v;
        __syncthreads();
    }
    int excl = sh[tid] - loc;
#pragma unroll 4
    for (int i = 0; i < SCANPER; i++) {
        int c = base + i;
        if (c < GC) {
            int v = g_cnt[cb][c];
            g_start[cb][c] = excl;
            excl += v;
        }
    }
    if (tid == 255) g_start[cb][GC] = sh[255];
}

// ---------- scatter into cell-sorted order (+ re-zero counters for next replay) ----------
__global__ __launch_bounds__(256) void scatter_kernel(const float* __restrict__ in1,
                                                      const float* __restrict__ in2,
                                                      int N, int M) {
    const int i = blockIdx.x * 256 + threadIdx.x;
    const int gsz = gridDim.x * 256;
    const int tot1 = NB * N;
    if (i < tot1 + NB * M) {
        const float* p;
        int cb, slot;
        if (i < tot1) { cb = i / N; slot = i - cb * N; p = in1 + (size_t)i * 3; }
        else {
            int j = i - tot1;
            cb = NB + j / M;
            slot = j - (cb - NB) * M;
            p = in2 + (size_t)j * 3;
        }
        const float x = p[0], y = p[1], z = p[2];
        const int pos = g_start[cb][g_cid[cb][slot]] + g_rnk[cb][slot];
        g_pts[cb][pos] = make_float4(x, y, z, 0.5f * (x * x + y * y + z * z));
    }
    for (int j = i; j < NCB * GC; j += gsz) ((int*)g_cnt)[j] = 0;
}

// ---------- thread-per-query exact NN search (R11 body) + fused final ----------
// Lane k <-> query k (cell-sorted): warp lanes walk the SAME rows in lockstep
// -> L1 broadcast. Box rows (z,y) are CONTIGUOUS ranges: [cs[rowb+x0],
// cs[rowb+x1+1]). t = h_p - q.p; d^2 = 2*(tmin + g_q). Unscanned cells are
// Chebyshev >= R+1 away -> separation >= R*GH (boundary-clamp safe).
__global__ __launch_bounds__(256) void search_kernel(float* __restrict__ out,
                                                     int N, int M,
                                                     float inv0, float inv1) {
    const int tid = threadIdx.x;
    const int i = blockIdx.x * 256 + tid;
    const int tot1 = NB * N;
    const int total = tot1 + NB * M;

    float contrib = 0.f;
    if (i < total) {
        int qcb, rcb;
        float wgt;
        if (i < tot1) { qcb = i / N; rcb = NB + qcb; wgt = inv1; }
        else { int j = i - tot1; qcb = NB + j / M; rcb = qcb - NB; wgt = inv0; }
        const int slot = (i < tot1) ? (i % N) : ((i - tot1) % M);

        const float4 q = g_pts[qcb][slot];
        const float nqx = -q.x, nqy = -q.y, nqz = -q.z, gq = q.w;
        const int cx = cellof(q.x), cy = cellof(q.y), cz = cellof(q.z);

        const float4* __restrict__ pts = g_pts[rcb];
        const int* __restrict__ cs = g_start[rcb];

        float tmin = FLT_MAX;
        float best;
        int R = 1;
        for (;; R++) {
            const int z0 = max(cz - R, 0), z1 = min(cz + R, G - 1);
            const int y0 = max(cy - R, 0), y1 = min(cy + R, G - 1);
            const int x0 = max(cx - R, 0), x1 = min(cx + R, G - 1);
            for (int z = z0; z <= z1; z++) {
                for (int y = y0; y <= y1; y++) {
                    const int rowb = (z * G + y) * G;
                    const int s = cs[rowb + x0];
                    const int e = cs[rowb + x1 + 1];
                    for (int k = s; k < e; k++) {
                        float4 p = pts[k];
                        float t = fmaf(p.x, nqx, fmaf(p.y, nqy, fmaf(p.z, nqz, p.w)));
                        tmin = fminf(tmin, t);
                    }
                }
            }
            best = fmaxf(0.f, 2.f * (tmin + gq));
            const float bd = (float)R * GH;
            if (best <= bd * bd || R >= G) break;
        }
        contrib = sqrtf(best) * wgt;
    }

    // Deterministic per-block reduction (fixed thread->query mapping).
    float acc = contrib;
#pragma unroll
    for (int off = 16; off > 0; off >>= 1)
        acc += __shfl_down_sync(0xFFFFFFFFu, acc, off);
    __shared__ float shf[8];
    __shared__ int amLast;
    if ((tid & 31) == 0) shf[tid >> 5] = acc;
    __syncthreads();
    if (tid < 8) {
        float v = shf[tid];
#pragma unroll
        for (int off = 4; off > 0; off >>= 1)
            v += __shfl_down_sync(0xFFu, v, off);
        if (tid == 0) g_part[blockIdx.x] = v;
    }

    // Last finished block performs the final fixed-order sum (deterministic).
    if (tid == 0) {
        __threadfence();
        amLast = (atomicAdd(&g_done, 1u) == gridDim.x - 1);
    }
    __syncthreads();
    if (amLast) {
        float a = 0.f;
        for (int k = tid; k < (int)gridDim.x; k += 256) a += g_part[k];
#pragma unroll
        for (int off = 16; off > 0; off >>= 1)
            a += __shfl_down_sync(0xFFFFFFFFu, a, off);
        if ((tid & 31) == 0) shf[tid >> 5] = a;
        __syncthreads();
        if (tid < 8) {
            float v = shf[tid];
#pragma unroll
            for (int off = 4; off > 0; off >>= 1)
                v += __shfl_down_sync(0xFFu, v, off);
            if (tid == 0) {
                out[0] = v;
                atomicExch(&g_done, 0u);  // reset for next graph replay
            }
        }
    }
}

extern "C" void kernel_launch(void* const* d_in, const int* in_sizes, int n_in,
                              void* d_out, int out_size) {
    const float* in1 = (const float*)d_in[0];  // [B, N, 3] cloud1
    const float* in2 = (const float*)d_in[1];  // [B, M, 3] cloud2
    const int N = in_sizes[0] / (NB * 3);
    const int M = in_sizes[1] / (NB * 3);
    const int total = NB * (N + M);
    const int nBlocks = (total + 255) / 256;  // 256 for the 8192/8192 shape

    count_kernel<<<nBlocks, 256>>>(in1, in2, N, M);
    scan_kernel<<<NCB, 256>>>(N, M);
    scatter_kernel<<<nBlocks, 256>>>(in1, in2, N, M);
    search_kernel<<<nBlocks, 256>>>((float*)d_out, N, M,
                                    1.f / (float)(NB * M), 1.f / (float)(NB * N));
}

// round 17
// speedup vs baseline: 1.2218x; 1.2218x over previous
#include <cuda_runtime.h>
#include <math.h>
#include <float.h>

#define G 20
#define GC (G * G * G)   // 8000
#define NB 4             // batches
#define NCB 8            // cloud*NB + b
#define NPC 8192         // max points per (cloud,batch)
#define GMIN (-5.0f)
#define GH 0.5f
#define GINV 2.0f
#define SCANPER 32       // 256*32 = 8192 >= GC

// Static scratch (no cudaMalloc). Zero-initialized at load; scatter_kernel
// re-zeroes g_cnt each execution so graph replays start clean.
__device__ int g_cnt[NCB][GC];
__device__ int g_start[NCB][GC + 1];
__device__ int g_rnk[NCB][NPC];
__device__ float4 g_pts[NCB][NPC];  // cell-sorted (x, y, z, |p|^2/2)
__device__ float g_part[512];

__device__ __forceinline__ int cellof(float x) {
    int c = (int)((x - GMIN) * GINV);
    return min(G - 1, max(0, c));
}

// ---------- count: rank per point (both clouds); cid recomputed later ----------
__global__ __launch_bounds__(256) void count_kernel(const float* __restrict__ in1,
                                                    const float* __restrict__ in2,
                                                    int N, int M) {
    const int i = blockIdx.x * 256 + threadIdx.x;
    const int tot1 = NB * N;
    if (i >= tot1 + NB * M) return;
    const float* p;
    int cb, slot;
    if (i < tot1) { cb = i / N; slot = i - cb * N; p = in1 + (size_t)i * 3; }
    else {
        int j = i - tot1;
        cb = NB + j / M;
        slot = j - (cb - NB) * M;
        p = in2 + (size_t)j * 3;
    }
    const int cid = (cellof(p[2]) * G + cellof(p[1])) * G + cellof(p[0]);
    g_rnk[cb][slot] = atomicAdd(&g_cnt[cb][cid], 1);
}

// ---------- scan: one block per (cloud,batch) ----------
__global__ __launch_bounds__(256) void scan_kernel(int N, int M) {
    const int cb = blockIdx.x;
    const int tid = threadIdx.x;
    const int base = tid * SCANPER;
    int loc = 0;
#pragma unroll 4
    for (int i = 0; i < SCANPER; i++) {
        int c = base + i;
        if (c < GC) loc += g_cnt[cb][c];
    }
    __shared__ int sh[256];
    sh[tid] = loc;
    __syncthreads();
    for (int off = 1; off < 256; off <<= 1) {
        int v = (tid >= off) ? sh[tid - off] : 0;
        __syncthreads();
        sh[tid] += v;
        __syncthreads();
    }
    int excl = sh[tid] - loc;
#pragma unroll 4
    for (int i = 0; i < SCANPER; i++) {
        int c = base + i;
        if (c < GC) {
            int v = g_cnt[cb][c];
            g_start[cb][c] = excl;
            excl += v;
        }
    }
    if (tid == 255) g_start[cb][GC] = sh[255];
}

// ---------- scatter (recomputes cid) + re-zero counters for next replay ----------
__global__ __launch_bounds__(256) void scatter_kernel(const float* __restrict__ in1,
                                                      const float* __restrict__ in2,
                                                      int N, int M) {
    const int i = blockIdx.x * 256 + threadIdx.x;
    const int gsz = gridDim.x * 256;
    const int tot1 = NB * N;
    if (i < tot1 + NB * M) {
        const float* p;
        int cb, slot;
        if (i < tot1) { cb = i / N; slot = i - cb * N; p = in1 + (size_t)i * 3; }
        else {
            int j = i - tot1;
            cb = NB + j / M;
            slot = j - (cb - NB) * M;
            p = in2 + (size_t)j * 3;
        }
        const float x = p[0], y = p[1], z = p[2];
        const int cid = (cellof(z) * G + cellof(y)) * G + cellof(x);
        const int pos = g_start[cb][cid] + g_rnk[cb][slot];
        g_pts[cb][pos] = make_float4(x, y, z, 0.5f * (x * x + y * y + z * z));
    }
    for (int j = i; j < NCB * GC; j += gsz) ((int*)g_cnt)[j] = 0;
}

// ---------- thread-per-query exact NN search (R11 golden body — DO NOT TOUCH) ----------
// Lane k <-> query k (cell-sorted): warp lanes walk the SAME rows in lockstep
// -> L1 broadcast. Box rows (z,y) are CONTIGUOUS ranges: [cs[rowb+x0],
// cs[rowb+x1+1]). t = h_p - q.p; d^2 = 2*(tmin + g_q). Unscanned cells are
// Chebyshev >= R+1 away -> separation >= R*GH (boundary-clamp safe).
__global__ __launch_bounds__(256) void search_kernel(int N, int M,
                                                     float inv0, float inv1) {
    const int i = blockIdx.x * 256 + threadIdx.x;
    const int tot1 = NB * N;
    const int total = tot1 + NB * M;

    float contrib = 0.f;
    if (i < total) {
        int qcb, rcb;
        float wgt;
        if (i < tot1) { qcb = i / N; rcb = NB + qcb; wgt = inv1; }
        else { int j = i - tot1; qcb = NB + j / M; rcb = qcb - NB; wgt = inv0; }
        const int slot = (i < tot1) ? (i % N) : ((i - tot1) % M);

        const float4 q = g_pts[qcb][slot];  // sorted order -> warp-coherent cells
        const float nqx = -q.x, nqy = -q.y, nqz = -q.z, gq = q.w;
        const int cx = cellof(q.x), cy = cellof(q.y), cz = cellof(q.z);

        const float4* __restrict__ pts = g_pts[rcb];
        const int* __restrict__ cs = g_start[rcb];

        float tmin = FLT_MAX;
        float best;
        int R = 1;
        for (;; R++) {
            const int z0 = max(cz - R, 0), z1 = min(cz + R, G - 1);
            const int y0 = max(cy - R, 0), y1 = min(cy + R, G - 1);
            const int x0 = max(cx - R, 0), x1 = min(cx + R, G - 1);
            for (int z = z0; z <= z1; z++) {
                for (int y = y0; y <= y1; y++) {
                    const int rowb = (z * G + y) * G;
                    const int s = cs[rowb + x0];
                    const int e = cs[rowb + x1 + 1];
                    for (int k = s; k < e; k++) {
                        float4 p = pts[k];
                        float t = fmaf(p.x, nqx, fmaf(p.y, nqy, fmaf(p.z, nqz, p.w)));
                        tmin = fminf(tmin, t);
                    }
                }
            }
            best = fmaxf(0.f, 2.f * (tmin + gq));
            const float bd = (float)R * GH;
            if (best <= bd * bd || R >= G) break;
        }
        contrib = sqrtf(best) * wgt;
    }

    // Deterministic per-block reduction (fixed thread->query mapping).
    float acc = contrib;
#pragma unroll
    for (int off = 16; off > 0; off >>= 1)
        acc += __shfl_down_sync(0xFFFFFFFFu, acc, off);
    __shared__ float shf[8];
    if ((threadIdx.x & 31) == 0) shf[threadIdx.x >> 5] = acc;
    __syncthreads();
    if (threadIdx.x < 8) {
        float v = shf[threadIdx.x];
#pragma unroll
        for (int off = 4; off > 0; off >>= 1)
            v += __shfl_down_sync(0xFFu, v, off);
        if (threadIdx.x == 0) g_part[blockIdx.x] = v;
    }
}

// ---------- final: fixed-order sum of block partials ----------
__global__ void final_kernel(float* __restrict__ out, int nPart) {
    float a = 0.f;
    for (int k = threadIdx.x; k < nPart; k += 256) a += g_part[k];
#pragma unroll
    for (int off = 16; off > 0; off >>= 1)
        a += __shfl_down_sync(0xFFFFFFFFu, a, off);
    __shared__ float s[8];
    if ((threadIdx.x & 31) == 0) s[threadIdx.x >> 5] = a;
    __syncthreads();
    if (threadIdx.x < 8) {
        float v = s[threadIdx.x];
#pragma unroll
        for (int off = 4; off > 0; off >>= 1)
            v += __shfl_down_sync(0xFFu, v, off);
        if (threadIdx.x == 0) out[0] = v;
    }
}

extern "C" void kernel_launch(void* const* d_in, const int* in_sizes, int n_in,
                              void* d_out, int out_size) {
    const float* in1 = (const float*)d_in[0];  // [B, N, 3] cloud1
    const float* in2 = (const float*)d_in[1];  // [B, M, 3] cloud2
    const int N = in_sizes[0] / (NB * 3);
    const int M = in_sizes[1] / (NB * 3);
    const int total = NB * (N + M);
    const int nBlocks = (total + 255) / 256;  // 256 for the 8192/8192 shape

    count_kernel<<<nBlocks, 256>>>(in1, in2, N, M);
    scan_kernel<<<NCB, 256>>>(N, M);
    scatter_kernel<<<nBlocks, 256>>>(in1, in2, N, M);
    search_kernel<<<nBlocks, 256>>>(N, M, 1.f / (float)(NB * M), 1.f / (float)(NB * N));
    final_kernel<<<1, 256>>>((float*)d_out, nBlocks);
}